// round 13
// baseline (speedup 1.0000x reference)
#include <cuda_runtime.h>
#include <cuda.h>

// ---- problem constants (L=512 fixed; B,T derived from sizes) ----
#define LFIX   512
#define TILE   64
#define NT     8
#define NPAIR  36            // NT*(NT+1)/2
#define MAXB   16
#define MAXT   32
#define SCONST 2.1972245773362196f   // log(9)

__device__ float g_rs [(size_t)(MAXT + 1) * MAXB * LFIX]; // per-step rowsums (atomic-accumulated)
__device__ int   g_bar[MAXB];                             // per-batch monotonic barrier counters

__device__ __forceinline__ float sigmoidf_(float v) { return 1.f / (1.f + __expf(-v)); }

// smem (floats): sMW 4096 | sM 4096 | sTA 4096 (SW128, 2x 64x32f) | sPC 1024 | sC 128
#define SMEM_FLOATS (4096 * 3 + 1024 + 128)

__device__ __forceinline__ void decode_pair(int p, int &ti, int &tj) {
    int t = 0;
    while (p >= NT - t) { p -= NT - t; t++; }
    ti = t; tj = t + p;
}

__device__ __forceinline__ unsigned smem_u32(const void* p) {
    unsigned a;
    asm("{ .reg .u64 t; cvta.to.shared.u64 t, %1; cvt.u32.u64 %0, t; }" : "=r"(a) : "l"(p));
    return a;
}

// half-warp (16-lane) row reduction: after this, every lane holds the sum
__device__ __forceinline__ float hw_sum(float v) {
    v += __shfl_xor_sync(0xffffffffu, v, 1);
    v += __shfl_xor_sync(0xffffffffu, v, 2);
    v += __shfl_xor_sync(0xffffffffu, v, 4);
    v += __shfl_xor_sync(0xffffffffu, v, 8);
    return v;
}

// SW128 index (in floats) for element (row i, col j) inside the 64x64 tile:
// sub-buffer h=j>>5 (2048 floats each); 16B group G=(j>>2)&7 XOR (i&7); elem j&3
__device__ __forceinline__ int sw_idx(int i, int j) {
    return ((j >> 5) << 11) + (i << 5) + 4 * (((j >> 2) & 7) ^ (i & 7)) + (j & 3);
}

__global__ void __launch_bounds__(256, 4) persist_kernel(
    float* __restrict__ out, const float* __restrict__ uin,
    const float* __restrict__ xin, int B, int T, int use_tma,
    const __grid_constant__ CUtensorMap tmap)
{
    extern __shared__ float sm[];
    float* sMW = sm;              // m*w tile, custom-swizzled (key tyy&7)
    float* sM  = sMW + 4096;      // m tile, same layout
    float* sTA = sM + 4096;       // s tile in TMA SW128 layout (2 sub-buffers)
    float* sPC = sTA + 4096;      // col-sum partials [tyy][j] (16 x 64)
    float* sC  = sPC + 1024;      // c_i (0..63), c_j (64..127)

    const int job = blockIdx.x;
    const int b = job / NPAIR;
    int p = job % NPAIR;
    int ti, tj; decode_pair(p, ti, tj);
    const bool diag = (ti == tj);
    const int tid = threadIdx.x;
    const int tx = tid & 15, tyy = tid >> 4;
    const int i0 = 4 * tyy, j0 = 4 * tx;
    const int L = LFIX;
    const size_t usz   = (size_t)B * L * L;
    const size_t mbase = (size_t)b * L * L;
    const int stride = B * L;
    const int swzg = 4 * (tx ^ (tyy & 7));   // layout for sMW/sM (unchanged)

    const float* uA = uin + mbase + (size_t)(ti * TILE) * L + tj * TILE;
    const float* uB = uin + mbase + (size_t)(tj * TILE) * L + ti * TILE;

    float ah1[16], ah2[16];
    float lam = 0.f;

    // ================= init: u_mod, a_hat0, w, m, s0 rowsums =================
    {
        float4 u2v[4], xj[4];
        #pragma unroll
        for (int jj = 0; jj < 4; jj++) {
            u2v[jj] = *(const float4*)&uB[(size_t)(j0 + jj) * L + i0];
            xj[jj]  = *(const float4*)&xin[(size_t)(b * L + tj * TILE + j0 + jj) * 4];
        }
        float cs4[4] = {0.f, 0.f, 0.f, 0.f};
        float rowp[4];
        #pragma unroll
        for (int ii = 0; ii < 4; ii++) {
            const int i = i0 + ii, gi = ti * TILE + i;
            float4 u1v = *(const float4*)&uA[(size_t)i * L + j0];
            float4 xi  = *(const float4*)&xin[(size_t)(b * L + ti * TILE + i) * 4];
            float mw4[4], m4[4];
            float rp = 0.f;
            #pragma unroll
            for (int jj = 0; jj < 4; jj++) {
                const int gj = tj * TILE + j0 + jj;
                float u1 = ((const float*)&u1v)[jj];
                float u2 = ((const float*)&u2v[jj])[ii];
                float um1 = sigmoidf_(2.f * (u1 - SCONST)) * u1;
                float um2 = sigmoidf_(2.f * (u2 - SCONST)) * u2;
                float a1 = sigmoidf_(um1) * sigmoidf_(2.f * (um1 - SCONST));
                float a2 = sigmoidf_(um2) * sigmoidf_(2.f * (um2 - SCONST));
                ah1[ii * 4 + jj] = a1;
                ah2[ii * 4 + jj] = a2;
                float w = 0.5f * (um1 + um2);
                int d = gi - gj; if (d < 0) d = -d;
                float m = 0.f;
                if (d > 3) {
                    float A2 = ((const float*)&xj[jj])[0], U2 = ((const float*)&xj[jj])[1];
                    float C2 = ((const float*)&xj[jj])[2], G2 = ((const float*)&xj[jj])[3];
                    m = xi.x * U2 + xi.y * A2 + xi.z * G2 + xi.w * C2 + xi.y * G2 + xi.w * U2;
                }
                m4[jj]  = m;
                mw4[jj] = m * w;
                float s = 0.5f * m * (a1 * a1 + a2 * a2);
                rp += s;
                cs4[jj] += s;
            }
            rowp[ii] = rp;
            *(float4*)&sMW[i * 64 + swzg] = make_float4(mw4[0], mw4[1], mw4[2], mw4[3]);
            *(float4*)&sM [i * 64 + swzg] = make_float4(m4[0], m4[1], m4[2], m4[3]);
        }
        float* rs0 = g_rs + (size_t)b * L;
        #pragma unroll
        for (int ii = 0; ii < 4; ii++) rowp[ii] = hw_sum(rowp[ii]);
        if (tx < 4) atomicAdd(&rs0[ti * TILE + i0 + tx], rowp[tx]);
        if (!diag) {
            *(float4*)&sPC[tyy * 64 + j0] = make_float4(cs4[0], cs4[1], cs4[2], cs4[3]);
            __syncthreads();
            if (tid < 64) {
                float a0 = 0.f, a1_ = 0.f, a2_ = 0.f, a3_ = 0.f;
                #pragma unroll
                for (int q = 0; q < 16; q += 4) {
                    a0 += sPC[(q + 0) * 64 + tid];
                    a1_ += sPC[(q + 1) * 64 + tid];
                    a2_ += sPC[(q + 2) * 64 + tid];
                    a3_ += sPC[(q + 3) * 64 + tid];
                }
                atomicAdd(&rs0[tj * TILE + tid], a0 + a1_ + a2_ + a3_);
            }
        }
        __syncthreads();
        if (tid == 0) { __threadfence(); atomicAdd(&g_bar[b], 1); }
    }

    const unsigned sTA_u32 = smem_u32(sTA);
    unsigned long long pol = 0;
    if (use_tma)
        asm("createpolicy.fractional.L2::evict_first.b64 %0, 1.0;" : "=l"(pol));

    // ================= T optimization steps =================
    float alpha = 0.01f, beta_run = 0.1f;
    for (int t = 0; t < T; t++) {
        const float tau = alpha * 0.99f;

        // ---- wait: round-t rowsums ready; drain prior TMA before sTA reuse ----
        if (tid == 0) {
            const int tgt = NPAIR * (t + 1);
            volatile int* c = g_bar + b;
            while (*c < tgt) __nanosleep(32);
            __threadfence();
            if (use_tma) asm volatile("cp.async.bulk.wait_group 0;" ::: "memory");
        }
        __syncthreads();

        // ---- lambda_t, c_t ----
        if (tid < 128) {
            int row = (tid < 64) ? (ti * TILE + tid) : (tj * TILE + (tid - 64));
            float rst = __ldcg(&g_rs[(size_t)t * stride + (size_t)b * L + row]);
            float rl = fmaxf(rst - 1.f, 0.f);
            lam = (t == 0) ? rl : (lam + beta_run * rl);
            sC[tid] = lam * sigmoidf_(2.f * (rst - 1.f));
        }
        __syncthreads();

        float4 ci4 = *(const float4*)&sC[i0];
        float4 cj4 = *(const float4*)&sC[64 + j0];
        float cs4[4] = {0.f, 0.f, 0.f, 0.f};
        float rowp[4];
        float* outT = out + (size_t)t * usz + mbase;

        // ---- update; s -> sTA (SW128) + in-register row partials ----
        #pragma unroll
        for (int ii = 0; ii < 4; ii++) {
            const int i = i0 + ii;
            float4 mw4 = *(const float4*)&sMW[i * 64 + swzg];
            float4 m4  = *(const float4*)&sM [i * 64 + swzg];
            const float ci = ((const float*)&ci4)[ii];
            float s4[4];
            float rp = 0.f;
            #pragma unroll
            for (int jj = 0; jj < 4; jj++) {
                float m  = ((const float*)&m4)[jj];
                float mw = ((const float*)&mw4)[jj];
                float cc = ci + ((const float*)&cj4)[jj];
                float q  = fmaf(m, cc, -mw);
                float f  = fmaf(-alpha, q, 1.0f);
                float n1 = fminf(fmaxf(fabsf(ah1[ii * 4 + jj] * f) - tau, 0.f), 1.f);
                float n2 = fminf(fmaxf(fabsf(ah2[ii * 4 + jj] * f) - tau, 0.f), 1.f);
                ah1[ii * 4 + jj] = n1;
                ah2[ii * 4 + jj] = n2;
                float s = 0.5f * m * fmaf(n1, n1, n2 * n2);
                s4[jj] = s;
                rp += s;
                cs4[jj] += s;
            }
            rowp[ii] = rp;
            // SW128 write: sub-buffer tx>>3, group (tx&7)^(i&7)
            *(float4*)&sTA[((tx >> 3) << 11) + (i << 5) + 4 * ((tx & 7) ^ (i & 7))] =
                make_float4(s4[0], s4[1], s4[2], s4[3]);
        }

        // ---- reductions for round t+1 + release ----
        if (t + 1 < T) {
            float* rsn = g_rs + (size_t)(t + 1) * stride + (size_t)b * L;
            #pragma unroll
            for (int ii = 0; ii < 4; ii++) rowp[ii] = hw_sum(rowp[ii]);
            if (tx < 4) atomicAdd(&rsn[ti * TILE + i0 + tx], rowp[tx]);
            if (!diag) {
                *(float4*)&sPC[tyy * 64 + j0] = make_float4(cs4[0], cs4[1], cs4[2], cs4[3]);
                __syncthreads();
                if (tid < 64) {
                    float a0 = 0.f, a1_ = 0.f, a2_ = 0.f, a3_ = 0.f;
                    #pragma unroll
                    for (int q = 0; q < 16; q += 4) {
                        a0 += sPC[(q + 0) * 64 + tid];
                        a1_ += sPC[(q + 1) * 64 + tid];
                        a2_ += sPC[(q + 2) * 64 + tid];
                        a3_ += sPC[(q + 3) * 64 + tid];
                    }
                    atomicAdd(&rsn[tj * TILE + tid], a0 + a1_ + a2_ + a3_);
                }
            }
            __syncthreads();
            if (tid == 0) { __threadfence(); atomicAdd(&g_bar[b], 1); }
            __syncthreads();   // all threads see completed sTA before stores below
        } else {
            __syncthreads();
        }

        // ---- A tile store: TMA (async engine) or STG fallback ----
        if (use_tma) {
            if (tid == 0) {
                asm volatile("fence.proxy.async;" ::: "memory");
                const int zc = t * B + b;
                const int yc = ti * TILE;
                #pragma unroll
                for (int h = 0; h < 2; h++) {
                    const int xc = tj * TILE + 32 * h;
                    asm volatile(
                        "cp.async.bulk.tensor.3d.global.shared::cta.tile.bulk_group"
                        ".L2::cache_hint [%0, {%1, %2, %3}], [%4], %5;"
                        :: "l"(&tmap), "r"(xc), "r"(yc), "r"(zc),
                           "r"(sTA_u32 + (unsigned)(h * 8192)), "l"(pol)
                        : "memory");
                }
                asm volatile("cp.async.bulk.commit_group;" ::: "memory");
            }
        } else {
            const int r = tid >> 2, seg = tid & 3;
            #pragma unroll
            for (int k = 0; k < 4; k++) {
                const int G = 4 * seg + k;   // 16B group index 0..15
                float4 v = *(const float4*)&sTA[((G >> 3) << 11) + (r << 5) + 4 * ((G & 7) ^ (r & 7))];
                __stcs((float4*)&outT[(size_t)(ti * TILE + r) * L + tj * TILE + 4 * G], v);
            }
        }

        // ---- B (transposed) tile store: column-slice gather from sTA ----
        if (!diag) {
            const int j = tid & 63, qr = tid >> 6;
            float vv[16];
            #pragma unroll
            for (int k = 0; k < 16; k++) {
                const int i = 16 * qr + k;
                vv[k] = sTA[sw_idx(i, j)];
            }
            float* dst = &outT[(size_t)(tj * TILE + j) * L + ti * TILE + 16 * qr];
            __stcs((float4*)(dst + 0),  make_float4(vv[0],  vv[1],  vv[2],  vv[3]));
            __stcs((float4*)(dst + 4),  make_float4(vv[4],  vv[5],  vv[6],  vv[7]));
            __stcs((float4*)(dst + 8),  make_float4(vv[8],  vv[9],  vv[10], vv[11]));
            __stcs((float4*)(dst + 12), make_float4(vv[12], vv[13], vv[14], vv[15]));
        }

        if (t > 0) beta_run *= 0.99f;
        alpha *= 0.99f;
    }

    if (use_tma && tid == 0)
        asm volatile("cp.async.bulk.wait_group 0;" ::: "memory");
}

// ---------------- host ----------------
typedef CUresult (*EncodeFn)(CUtensorMap*, CUtensorMapDataType, cuuint32_t, void*,
                             const cuuint64_t*, const cuuint64_t*, const cuuint32_t*,
                             const cuuint32_t*, CUtensorMapInterleave, CUtensorMapSwizzle,
                             CUtensorMapL2promotion, CUtensorMapFloatOOBfill);

extern "C" void kernel_launch(void* const* d_in, const int* in_sizes, int n_in,
                              void* d_out, int out_size)
{
    int iu = 0;
    for (int i = 1; i < n_in; i++) if (in_sizes[i] > in_sizes[iu]) iu = i;
    int ix = -1;
    for (int i = 0; i < n_in; i++) {
        if (i == iu) continue;
        if (ix < 0 || in_sizes[i] > in_sizes[ix]) ix = i;
    }
    const float* u = (const float*)d_in[iu];
    const float* x = (const float*)d_in[ix];
    const long long usz = in_sizes[iu];
    const long long xsz = in_sizes[ix];
    const int L = (int)(4LL * usz / xsz);           // 512
    const int B = (int)(xsz / (4LL * L));           // 16
    const int T = (int)((long long)out_size / usz); // 20
    float* out = (float*)d_out;

    // tensormap for out viewed as [T*B, L, L] f32, SW128 boxes of 32x64
    CUtensorMap map;
    memset(&map, 0, sizeof(map));
    int use_tma = 0;
    {
        void* sym = nullptr;
        cudaDriverEntryPointQueryResult qr;
        if (cudaGetDriverEntryPointByVersion("cuTensorMapEncodeTiled", &sym, 12000,
                                             cudaEnableDefault, &qr) == cudaSuccess && sym) {
            cuuint64_t dims[3]    = {(cuuint64_t)L, (cuuint64_t)L, (cuuint64_t)((long long)T * B)};
            cuuint64_t strides[2] = {(cuuint64_t)L * 4, (cuuint64_t)L * L * 4};
            cuuint32_t box[3]     = {32, 64, 1};
            cuuint32_t es[3]      = {1, 1, 1};
            CUresult r = ((EncodeFn)sym)(&map, CU_TENSOR_MAP_DATA_TYPE_FLOAT32, 3, out,
                                         dims, strides, box, es,
                                         CU_TENSOR_MAP_INTERLEAVE_NONE,
                                         CU_TENSOR_MAP_SWIZZLE_128B,
                                         CU_TENSOR_MAP_L2_PROMOTION_L2_128B,
                                         CU_TENSOR_MAP_FLOAT_OOB_FILL_NONE);
            use_tma = (r == CUDA_SUCCESS) ? 1 : 0;
        }
    }

    void* rs_ptr = nullptr;  cudaGetSymbolAddress(&rs_ptr, g_rs);
    void* bar_ptr = nullptr; cudaGetSymbolAddress(&bar_ptr, g_bar);
    cudaMemsetAsync(rs_ptr, 0, sizeof(float) * (size_t)(T + 1) * B * L);
    cudaMemsetAsync(bar_ptr, 0, sizeof(int) * MAXB);

    const int smem_bytes = SMEM_FLOATS * sizeof(float);
    cudaFuncSetAttribute(persist_kernel, cudaFuncAttributeMaxDynamicSharedMemorySize, smem_bytes);

    persist_kernel<<<B * NPAIR, 256, smem_bytes>>>(out, u, x, B, T, use_tma, map);
}

// round 14
// speedup vs baseline: 1.2546x; 1.2546x over previous
#include <cuda_runtime.h>

// ---- problem constants (L=512 fixed; B,T derived from sizes) ----
#define LFIX   512
#define TILE   64
#define NT     8
#define NPAIR  36            // NT*(NT+1)/2
#define MAXB   16
#define MAXT   32
#define SCONST 2.1972245773362196f   // log(9)

__device__ float g_rs [(size_t)(MAXT + 1) * MAXB * LFIX]; // per-step rowsums (atomic-accumulated)
__device__ int   g_bar[MAXB];                             // per-batch monotonic barrier counters

__device__ __forceinline__ float sigmoidf_(float v) { return 1.f / (1.f + __expf(-v)); }

// smem (floats): sMW 4096 | sM 4096 | sA 4096 | sPC 1024 | sC 128
#define SMEM_FLOATS (4096 * 3 + 1024 + 128)

__device__ __forceinline__ void decode_pair(int p, int &ti, int &tj) {
    int t = 0;
    while (p >= NT - t) { p -= NT - t; t++; }
    ti = t; tj = t + p;
}

// arrive: CTA-scope release at bar.sync, then gpu fence + RED by one thread
__device__ __forceinline__ void batch_arrive(int b) {
    __syncthreads();
    if (threadIdx.x == 0) {
        __threadfence();
        atomicAdd(&g_bar[b], 1);
    }
}
__device__ __forceinline__ void batch_wait(int b, int target) {
    if (threadIdx.x == 0) {
        volatile int* c = g_bar + b;
        while (*c < target) __nanosleep(32);
        __threadfence();
    }
    __syncthreads();
}

__global__ void __launch_bounds__(256, 4) persist_kernel(
    float* __restrict__ out, const float* __restrict__ uin,
    const float* __restrict__ xin, int B, int T)
{
    extern __shared__ float sm[];
    float* sMW = sm;              // m*w tile, i-major swizzled
    float* sM  = sMW + 4096;      // m tile, i-major swizzled
    float* sA  = sM + 4096;       // s staging, i-major swizzled (B-transpose source)
    float* sPC = sA + 4096;       // col-sum partials [tyy][j] (16 x 64)
    float* sC  = sPC + 1024;      // c_i (0..63), c_j (64..127)

    const int job = blockIdx.x;
    const int b = job / NPAIR;
    int p = job % NPAIR;
    int ti, tj; decode_pair(p, ti, tj);
    const bool diag = (ti == tj);
    const int tid = threadIdx.x;
    const int tx = tid & 15, tyy = tid >> 4;
    const int i0 = 4 * tyy, j0 = 4 * tx;
    const int L = LFIX;
    const size_t usz   = (size_t)B * L * L;
    const size_t mbase = (size_t)b * L * L;
    const int stride = B * L;
    const int swzg = 4 * (tx ^ (tyy & 7));

    const float* uA = uin + mbase + (size_t)(ti * TILE) * L + tj * TILE;
    const float* uB = uin + mbase + (size_t)(tj * TILE) * L + ti * TILE;

    float ah1[16], ah2[16];   // a_hat(i,j) / a_hat(j,i), persistent in registers
    float lam = 0.f;

    // ================= init: u_mod, a_hat0, w, m, s0 =================
    {
        float4 u2v[4], xj[4];
        #pragma unroll
        for (int jj = 0; jj < 4; jj++) {
            u2v[jj] = *(const float4*)&uB[(size_t)(j0 + jj) * L + i0];
            xj[jj]  = *(const float4*)&xin[(size_t)(b * L + tj * TILE + j0 + jj) * 4];
        }
        float cs4[4] = {0.f, 0.f, 0.f, 0.f};
        #pragma unroll
        for (int ii = 0; ii < 4; ii++) {
            const int i = i0 + ii, gi = ti * TILE + i;
            float4 u1v = *(const float4*)&uA[(size_t)i * L + j0];
            float4 xi  = *(const float4*)&xin[(size_t)(b * L + ti * TILE + i) * 4];
            float mw4[4], m4[4], s4[4];
            #pragma unroll
            for (int jj = 0; jj < 4; jj++) {
                const int gj = tj * TILE + j0 + jj;
                float u1 = ((const float*)&u1v)[jj];
                float u2 = ((const float*)&u2v[jj])[ii];
                float um1 = sigmoidf_(2.f * (u1 - SCONST)) * u1;
                float um2 = sigmoidf_(2.f * (u2 - SCONST)) * u2;
                float a1 = sigmoidf_(um1) * sigmoidf_(2.f * (um1 - SCONST));
                float a2 = sigmoidf_(um2) * sigmoidf_(2.f * (um2 - SCONST));
                ah1[ii * 4 + jj] = a1;
                ah2[ii * 4 + jj] = a2;
                float w = 0.5f * (um1 + um2);
                int d = gi - gj; if (d < 0) d = -d;
                float m = 0.f;
                if (d > 3) {
                    float A2 = ((const float*)&xj[jj])[0], U2 = ((const float*)&xj[jj])[1];
                    float C2 = ((const float*)&xj[jj])[2], G2 = ((const float*)&xj[jj])[3];
                    m = xi.x * U2 + xi.y * A2 + xi.z * G2 + xi.w * C2 + xi.y * G2 + xi.w * U2;
                }
                m4[jj]  = m;
                mw4[jj] = m * w;
                float s = 0.5f * m * (a1 * a1 + a2 * a2);
                s4[jj] = s;
                cs4[jj] += s;
            }
            *(float4*)&sMW[i * 64 + swzg] = make_float4(mw4[0], mw4[1], mw4[2], mw4[3]);
            *(float4*)&sM [i * 64 + swzg] = make_float4(m4[0], m4[1], m4[2], m4[3]);
            *(float4*)&sA [i * 64 + swzg] = make_float4(s4[0], s4[1], s4[2], s4[3]);
        }
        if (!diag)
            *(float4*)&sPC[tyy * 64 + j0] = make_float4(cs4[0], cs4[1], cs4[2], cs4[3]);
        __syncthreads();

        // rowsum reductions -> g_rs[0]
        float* rs0 = g_rs + (size_t)b * L;
        if (tid < 64) {
            float4 acc = make_float4(0.f, 0.f, 0.f, 0.f);
            #pragma unroll
            for (int g = 0; g < 16; g++) {
                int gg = (g + tid) & 15;
                float4 v = *(const float4*)&sA[tid * 64 + 4 * gg];
                acc.x += v.x; acc.y += v.y; acc.z += v.z; acc.w += v.w;
            }
            atomicAdd(&rs0[ti * TILE + tid], acc.x + acc.y + acc.z + acc.w);
        } else if (tid < 128 && !diag) {
            int j = tid - 64;
            float a0 = 0.f, a1_ = 0.f, a2_ = 0.f, a3_ = 0.f;
            #pragma unroll
            for (int q = 0; q < 16; q += 4) {
                a0 += sPC[(q + 0) * 64 + j];
                a1_ += sPC[(q + 1) * 64 + j];
                a2_ += sPC[(q + 2) * 64 + j];
                a3_ += sPC[(q + 3) * 64 + j];
            }
            atomicAdd(&rs0[tj * TILE + j], a0 + a1_ + a2_ + a3_);
        }
        batch_arrive(b);
    }

    // ================= T optimization steps =================
    float alpha = 0.01f, beta_run = 0.1f;
    for (int t = 0; t < T; t++) {
        const float tau = alpha * 0.99f;    // RHO * alpha * DECAY

        batch_wait(b, NPAIR * (t + 1));     // round-t rowsums ready

        // ---- lambda_t, c_t for this block's 128 rows ----
        if (tid < 128) {
            int row = (tid < 64) ? (ti * TILE + tid) : (tj * TILE + (tid - 64));
            float rst = __ldcg(&g_rs[(size_t)t * stride + (size_t)b * L + row]);
            float rl = fmaxf(rst - 1.f, 0.f);
            lam = (t == 0) ? rl : (lam + beta_run * rl);
            sC[tid] = lam * sigmoidf_(2.f * (rst - 1.f));
        }
        __syncthreads();

        float4 ci4 = *(const float4*)&sC[i0];
        float4 cj4 = *(const float4*)&sC[64 + j0];
        float cs4[4] = {0.f, 0.f, 0.f, 0.f};
        float* outT = out + (size_t)t * usz + mbase;

        // ---- update; A-tile stcs from registers; s -> sA only if B-mirror needed ----
        #pragma unroll
        for (int ii = 0; ii < 4; ii++) {
            const int i = i0 + ii;
            float4 mw4 = *(const float4*)&sMW[i * 64 + swzg];
            float4 m4  = *(const float4*)&sM [i * 64 + swzg];
            const float ci = ((const float*)&ci4)[ii];
            float s4[4];
            #pragma unroll
            for (int jj = 0; jj < 4; jj++) {
                float m  = ((const float*)&m4)[jj];
                float mw = ((const float*)&mw4)[jj];
                float cc = ci + ((const float*)&cj4)[jj];
                float q  = fmaf(m, cc, -mw);           // m*(ci+cj) - m*w
                float f  = fmaf(-alpha, q, 1.0f);      // 1 - alpha*(...)
                float n1 = fminf(fmaxf(fabsf(ah1[ii * 4 + jj] * f) - tau, 0.f), 1.f);
                float n2 = fminf(fmaxf(fabsf(ah2[ii * 4 + jj] * f) - tau, 0.f), 1.f);
                ah1[ii * 4 + jj] = n1;
                ah2[ii * 4 + jj] = n2;
                float s = 0.5f * m * fmaf(n1, n1, n2 * n2);
                s4[jj] = s;
                cs4[jj] += s;
            }
            float4 sv = make_float4(s4[0], s4[1], s4[2], s4[3]);
            if (!diag) *(float4*)&sA[i * 64 + swzg] = sv;
            __stcs((float4*)&outT[(size_t)(ti * TILE + i) * L + tj * TILE + j0], sv);
        }
        if (!diag)
            *(float4*)&sPC[tyy * 64 + j0] = make_float4(cs4[0], cs4[1], cs4[2], cs4[3]);
        __syncthreads();

        // ---- rowsum reductions for round t+1, then RELEASE ----
        if (t + 1 < T) {
            float* rsn = g_rs + (size_t)(t + 1) * stride + (size_t)b * L;
            if (tid < 64) {
                if (diag) {
                    // diag: row sums come from out-row? sA not written; recompute from A row
                    // (diag blocks still need row sums; gather from outT is global — instead
                    //  reconstruct from registers via warp layout is complex; use sPC path)
                }
                float4 acc = make_float4(0.f, 0.f, 0.f, 0.f);
                if (!diag) {
                    #pragma unroll
                    for (int g = 0; g < 16; g++) {
                        int gg = (g + tid) & 15;
                        float4 v = *(const float4*)&sA[tid * 64 + 4 * gg];
                        acc.x += v.x; acc.y += v.y; acc.z += v.z; acc.w += v.w;
                    }
                    atomicAdd(&rsn[ti * TILE + tid], acc.x + acc.y + acc.z + acc.w);
                }
            }
            if (diag) {
                // diag blocks: row sums via sPC (column sums == row sums by symmetry of tile)
                // sPC holds per-tyy column partials only for !diag; for diag we use a
                // dedicated path: each thread's cs4 are partial COLUMN sums of its 4 cols,
                // and for a diagonal tile rowsum == colsum.
                *(float4*)&sPC[tyy * 64 + j0] = make_float4(cs4[0], cs4[1], cs4[2], cs4[3]);
                __syncthreads();
                if (tid < 64) {
                    float a0 = 0.f, a1_ = 0.f, a2_ = 0.f, a3_ = 0.f;
                    #pragma unroll
                    for (int q = 0; q < 16; q += 4) {
                        a0 += sPC[(q + 0) * 64 + tid];
                        a1_ += sPC[(q + 1) * 64 + tid];
                        a2_ += sPC[(q + 2) * 64 + tid];
                        a3_ += sPC[(q + 3) * 64 + tid];
                    }
                    atomicAdd(&rsn[ti * TILE + tid], a0 + a1_ + a2_ + a3_);
                }
            } else if (tid >= 64 && tid < 128) {
                int j = tid - 64;
                float a0 = 0.f, a1_ = 0.f, a2_ = 0.f, a3_ = 0.f;
                #pragma unroll
                for (int q = 0; q < 16; q += 4) {
                    a0 += sPC[(q + 0) * 64 + j];
                    a1_ += sPC[(q + 1) * 64 + j];
                    a2_ += sPC[(q + 2) * 64 + j];
                    a3_ += sPC[(q + 3) * 64 + j];
                }
                atomicAdd(&rsn[tj * TILE + j], a0 + a1_ + a2_ + a3_);
            }
            batch_arrive(b);   // release BEFORE the bulk B-tile stores
        }

        // ---- B (transposed) tile store (off the inter-block critical path) ----
        if (!diag) {
            #pragma unroll
            for (int jj = 0; jj < 4; jj++) {
                const int j = 4 * tyy + jj;
                const int goff = 4 * (tyy ^ (tx & 7)) + jj;
                float4 v;
                v.x = sA[(4 * tx + 0) * 64 + goff];
                v.y = sA[(4 * tx + 1) * 64 + goff];
                v.z = sA[(4 * tx + 2) * 64 + goff];
                v.w = sA[(4 * tx + 3) * 64 + goff];
                __stcs((float4*)&outT[(size_t)(tj * TILE + j) * L + ti * TILE + 4 * tx], v);
            }
        }

        if (t > 0) beta_run *= 0.99f;
        alpha *= 0.99f;
    }
}

// ---------------- host ----------------
extern "C" void kernel_launch(void* const* d_in, const int* in_sizes, int n_in,
                              void* d_out, int out_size)
{
    // identify inputs by size: u = largest, x = next largest
    int iu = 0;
    for (int i = 1; i < n_in; i++) if (in_sizes[i] > in_sizes[iu]) iu = i;
    int ix = -1;
    for (int i = 0; i < n_in; i++) {
        if (i == iu) continue;
        if (ix < 0 || in_sizes[i] > in_sizes[ix]) ix = i;
    }
    const float* u = (const float*)d_in[iu];
    const float* x = (const float*)d_in[ix];
    const long long usz = in_sizes[iu];
    const long long xsz = in_sizes[ix];
    const int L = (int)(4LL * usz / xsz);           // 512
    const int B = (int)(xsz / (4LL * L));           // 16
    const int T = (int)((long long)out_size / usz); // 20
    float* out = (float*)d_out;

    void* rs_ptr = nullptr;  cudaGetSymbolAddress(&rs_ptr, g_rs);
    void* bar_ptr = nullptr; cudaGetSymbolAddress(&bar_ptr, g_bar);
    cudaMemsetAsync(rs_ptr, 0, sizeof(float) * (size_t)(T + 1) * B * L);
    cudaMemsetAsync(bar_ptr, 0, sizeof(int) * MAXB);

    const int smem_bytes = SMEM_FLOATS * sizeof(float);
    cudaFuncSetAttribute(persist_kernel, cudaFuncAttributeMaxDynamicSharedMemorySize, smem_bytes);

    persist_kernel<<<B * NPAIR, 256, smem_bytes>>>(out, u, x, B, T);
}

// round 16
// speedup vs baseline: 1.3180x; 1.0505x over previous
#include <cuda_runtime.h>

// ---- problem constants (L=512 fixed; B,T derived from sizes) ----
#define LFIX   512
#define TILE   64
#define NT     8
#define NPAIR  36            // NT*(NT+1)/2
#define MAXB   16
#define MAXT   32
#define SCONST 2.1972245773362196f   // log(9)

__device__ float g_rs [(size_t)(MAXT + 1) * MAXB * LFIX]; // per-step rowsums (atomic-accumulated)
__device__ int   g_bar[MAXB];                             // per-batch monotonic barrier counters

__device__ __forceinline__ float sigmoidf_(float v) { return 1.f / (1.f + __expf(-v)); }

// smem (floats): sMW 4096 | sM 4096 | sA 4096 | sPC 1024 | sC 128
#define SMEM_FLOATS (4096 * 3 + 1024 + 128)

__device__ __forceinline__ void decode_pair(int p, int &ti, int &tj) {
    int t = 0;
    while (p >= NT - t) { p -= NT - t; t++; }
    ti = t; tj = t + p;
}

// arrive: CTA-scope release at bar.sync, then gpu fence + RED by one thread
__device__ __forceinline__ void batch_arrive(int b) {
    __syncthreads();
    if (threadIdx.x == 0) {
        __threadfence();
        atomicAdd(&g_bar[b], 1);
    }
}
__device__ __forceinline__ void batch_wait(int b, int target) {
    if (threadIdx.x == 0) {
        volatile int* c = g_bar + b;
        while (*c < target) __nanosleep(32);
        __threadfence();
    }
    __syncthreads();
}

__global__ void __launch_bounds__(256, 4) persist_kernel(
    float* __restrict__ out, const float* __restrict__ uin,
    const float* __restrict__ xin, int B, int T)
{
    extern __shared__ float sm[];
    float* sMW = sm;              // m*w tile, i-major swizzled
    float* sM  = sMW + 4096;      // m tile, i-major swizzled
    float* sA  = sM + 4096;       // s staging, i-major swizzled
    float* sPC = sA + 4096;       // col-sum partials [tyy][j] (16 x 64)
    float* sC  = sPC + 1024;      // c_i (0..63), c_j (64..127)

    const int job = blockIdx.x;
    const int b = job / NPAIR;
    int p = job % NPAIR;
    int ti, tj; decode_pair(p, ti, tj);
    const bool diag = (ti == tj);
    const int tid = threadIdx.x;
    const int tx = tid & 15, tyy = tid >> 4;
    const int i0 = 4 * tyy, j0 = 4 * tx;
    const int L = LFIX;
    const size_t usz   = (size_t)B * L * L;
    const size_t mbase = (size_t)b * L * L;
    const int stride = B * L;
    const int swzg = 4 * (tx ^ (tyy & 7));

    const float* uA = uin + mbase + (size_t)(ti * TILE) * L + tj * TILE;
    const float* uB = uin + mbase + (size_t)(tj * TILE) * L + ti * TILE;

    float ah1[16], ah2[16];   // a_hat(i,j) / a_hat(j,i), persistent in registers
    float lam = 0.f;

    // ================= init: u_mod, a_hat0, w, m, s0 =================
    {
        float4 u2v[4], xj[4];
        #pragma unroll
        for (int jj = 0; jj < 4; jj++) {
            u2v[jj] = *(const float4*)&uB[(size_t)(j0 + jj) * L + i0];
            xj[jj]  = *(const float4*)&xin[(size_t)(b * L + tj * TILE + j0 + jj) * 4];
        }
        float cs4[4] = {0.f, 0.f, 0.f, 0.f};
        #pragma unroll
        for (int ii = 0; ii < 4; ii++) {
            const int i = i0 + ii, gi = ti * TILE + i;
            float4 u1v = *(const float4*)&uA[(size_t)i * L + j0];
            float4 xi  = *(const float4*)&xin[(size_t)(b * L + ti * TILE + i) * 4];
            float mw4[4], m4[4], s4[4];
            #pragma unroll
            for (int jj = 0; jj < 4; jj++) {
                const int gj = tj * TILE + j0 + jj;
                float u1 = ((const float*)&u1v)[jj];
                float u2 = ((const float*)&u2v[jj])[ii];
                float um1 = sigmoidf_(2.f * (u1 - SCONST)) * u1;
                float um2 = sigmoidf_(2.f * (u2 - SCONST)) * u2;
                float a1 = sigmoidf_(um1) * sigmoidf_(2.f * (um1 - SCONST));
                float a2 = sigmoidf_(um2) * sigmoidf_(2.f * (um2 - SCONST));
                ah1[ii * 4 + jj] = a1;
                ah2[ii * 4 + jj] = a2;
                float w = 0.5f * (um1 + um2);
                int d = gi - gj; if (d < 0) d = -d;
                float m = 0.f;
                if (d > 3) {
                    float A2 = ((const float*)&xj[jj])[0], U2 = ((const float*)&xj[jj])[1];
                    float C2 = ((const float*)&xj[jj])[2], G2 = ((const float*)&xj[jj])[3];
                    m = xi.x * U2 + xi.y * A2 + xi.z * G2 + xi.w * C2 + xi.y * G2 + xi.w * U2;
                }
                m4[jj]  = m;
                mw4[jj] = m * w;
                float s = 0.5f * m * (a1 * a1 + a2 * a2);
                s4[jj] = s;
                cs4[jj] += s;
            }
            *(float4*)&sMW[i * 64 + swzg] = make_float4(mw4[0], mw4[1], mw4[2], mw4[3]);
            *(float4*)&sM [i * 64 + swzg] = make_float4(m4[0], m4[1], m4[2], m4[3]);
            *(float4*)&sA [i * 64 + swzg] = make_float4(s4[0], s4[1], s4[2], s4[3]);
        }
        if (!diag)
            *(float4*)&sPC[tyy * 64 + j0] = make_float4(cs4[0], cs4[1], cs4[2], cs4[3]);
        __syncthreads();

        // rowsum reductions -> g_rs[0]
        float* rs0 = g_rs + (size_t)b * L;
        if (tid < 64) {
            float4 acc = make_float4(0.f, 0.f, 0.f, 0.f);
            #pragma unroll
            for (int g = 0; g < 16; g++) {
                int gg = (g + tid) & 15;
                float4 v = *(const float4*)&sA[tid * 64 + 4 * gg];
                acc.x += v.x; acc.y += v.y; acc.z += v.z; acc.w += v.w;
            }
            atomicAdd(&rs0[ti * TILE + tid], acc.x + acc.y + acc.z + acc.w);
        } else if (tid < 128 && !diag) {
            int j = tid - 64;
            float a0 = 0.f, a1_ = 0.f, a2_ = 0.f, a3_ = 0.f;
            #pragma unroll
            for (int q = 0; q < 16; q += 4) {
                a0 += sPC[(q + 0) * 64 + j];
                a1_ += sPC[(q + 1) * 64 + j];
                a2_ += sPC[(q + 2) * 64 + j];
                a3_ += sPC[(q + 3) * 64 + j];
            }
            atomicAdd(&rs0[tj * TILE + j], a0 + a1_ + a2_ + a3_);
        }
        batch_arrive(b);
    }

    // ---- batch phase stagger: desynchronize the 16 batches' store bursts ----
    {
        long long t0 = clock64();
        const long long dly = (long long)b * 700;   // ~390ns per batch index
        while (clock64() - t0 < dly) { }
    }

    // ================= T optimization steps =================
    float alpha = 0.01f, beta_run = 0.1f;
    for (int t = 0; t < T; t++) {
        const float tau = alpha * 0.99f;    // RHO * alpha * DECAY

        batch_wait(b, NPAIR * (t + 1));     // round-t rowsums ready

        // ---- lambda_t, c_t for this block's 128 rows ----
        if (tid < 128) {
            int row = (tid < 64) ? (ti * TILE + tid) : (tj * TILE + (tid - 64));
            float rst = __ldcg(&g_rs[(size_t)t * stride + (size_t)b * L + row]);
            float rl = fmaxf(rst - 1.f, 0.f);
            lam = (t == 0) ? rl : (lam + beta_run * rl);
            sC[tid] = lam * sigmoidf_(2.f * (rst - 1.f));
        }
        __syncthreads();

        float4 ci4 = *(const float4*)&sC[i0];
        float4 cj4 = *(const float4*)&sC[64 + j0];
        float cs4[4] = {0.f, 0.f, 0.f, 0.f};
        float* outT = out + (size_t)t * usz + mbase;

        // ---- update; s to smem only (no global stores before release) ----
        #pragma unroll
        for (int ii = 0; ii < 4; ii++) {
            const int i = i0 + ii;
            float4 mw4 = *(const float4*)&sMW[i * 64 + swzg];
            float4 m4  = *(const float4*)&sM [i * 64 + swzg];
            const float ci = ((const float*)&ci4)[ii];
            float s4[4];
            #pragma unroll
            for (int jj = 0; jj < 4; jj++) {
                float m  = ((const float*)&m4)[jj];
                float mw = ((const float*)&mw4)[jj];
                float cc = ci + ((const float*)&cj4)[jj];
                float q  = fmaf(m, cc, -mw);           // m*(ci+cj) - m*w
                float f  = fmaf(-alpha, q, 1.0f);      // 1 - alpha*(...)
                float n1 = fminf(fmaxf(fabsf(ah1[ii * 4 + jj] * f) - tau, 0.f), 1.f);
                float n2 = fminf(fmaxf(fabsf(ah2[ii * 4 + jj] * f) - tau, 0.f), 1.f);
                ah1[ii * 4 + jj] = n1;
                ah2[ii * 4 + jj] = n2;
                float s = 0.5f * m * fmaf(n1, n1, n2 * n2);
                s4[jj] = s;
                cs4[jj] += s;
            }
            *(float4*)&sA[i * 64 + swzg] = make_float4(s4[0], s4[1], s4[2], s4[3]);
        }
        if (!diag)
            *(float4*)&sPC[tyy * 64 + j0] = make_float4(cs4[0], cs4[1], cs4[2], cs4[3]);
        __syncthreads();

        // ---- rowsum reductions for round t+1, then RELEASE ----
        if (t + 1 < T) {
            float* rsn = g_rs + (size_t)(t + 1) * stride + (size_t)b * L;
            if (tid < 64) {
                float4 acc = make_float4(0.f, 0.f, 0.f, 0.f);
                #pragma unroll
                for (int g = 0; g < 16; g++) {
                    int gg = (g + tid) & 15;
                    float4 v = *(const float4*)&sA[tid * 64 + 4 * gg];
                    acc.x += v.x; acc.y += v.y; acc.z += v.z; acc.w += v.w;
                }
                atomicAdd(&rsn[ti * TILE + tid], acc.x + acc.y + acc.z + acc.w);
            } else if (tid < 128 && !diag) {
                int j = tid - 64;
                float a0 = 0.f, a1_ = 0.f, a2_ = 0.f, a3_ = 0.f;
                #pragma unroll
                for (int q = 0; q < 16; q += 4) {
                    a0 += sPC[(q + 0) * 64 + j];
                    a1_ += sPC[(q + 1) * 64 + j];
                    a2_ += sPC[(q + 2) * 64 + j];
                    a3_ += sPC[(q + 3) * 64 + j];
                }
                atomicAdd(&rsn[tj * TILE + j], a0 + a1_ + a2_ + a3_);
            }
            batch_arrive(b);   // release BEFORE the bulk output stores
        } else {
            __syncthreads();   // sA consistent before readback below
        }

        // ---- output stores (off the inter-block critical path) ----
        #pragma unroll
        for (int ii = 0; ii < 4; ii++) {     // A tile: read back own smem addresses
            const int i = i0 + ii;
            float4 sv = *(const float4*)&sA[i * 64 + swzg];
            __stcs((float4*)&outT[(size_t)(ti * TILE + i) * L + tj * TILE + j0], sv);
        }
        if (!diag) {                          // B (transposed) tile
            #pragma unroll
            for (int jj = 0; jj < 4; jj++) {
                const int j = 4 * tyy + jj;
                const int goff = 4 * (tyy ^ (tx & 7)) + jj;
                float4 v;
                v.x = sA[(4 * tx + 0) * 64 + goff];
                v.y = sA[(4 * tx + 1) * 64 + goff];
                v.z = sA[(4 * tx + 2) * 64 + goff];
                v.w = sA[(4 * tx + 3) * 64 + goff];
                __stcs((float4*)&outT[(size_t)(tj * TILE + j) * L + ti * TILE + 4 * tx], v);
            }
        }

        if (t > 0) beta_run *= 0.99f;
        alpha *= 0.99f;
    }
}

// ---------------- host ----------------
extern "C" void kernel_launch(void* const* d_in, const int* in_sizes, int n_in,
                              void* d_out, int out_size)
{
    // identify inputs by size: u = largest, x = next largest
    int iu = 0;
    for (int i = 1; i < n_in; i++) if (in_sizes[i] > in_sizes[iu]) iu = i;
    int ix = -1;
    for (int i = 0; i < n_in; i++) {
        if (i == iu) continue;
        if (ix < 0 || in_sizes[i] > in_sizes[ix]) ix = i;
    }
    const float* u = (const float*)d_in[iu];
    const float* x = (const float*)d_in[ix];
    const long long usz = in_sizes[iu];
    const long long xsz = in_sizes[ix];
    const int L = (int)(4LL * usz / xsz);           // 512
    const int B = (int)(xsz / (4LL * L));           // 16
    const int T = (int)((long long)out_size / usz); // 20
    float* out = (float*)d_out;

    void* rs_ptr = nullptr;  cudaGetSymbolAddress(&rs_ptr, g_rs);
    void* bar_ptr = nullptr; cudaGetSymbolAddress(&bar_ptr, g_bar);
    cudaMemsetAsync(rs_ptr, 0, sizeof(float) * (size_t)(T + 1) * B * L);
    cudaMemsetAsync(bar_ptr, 0, sizeof(int) * MAXB);

    const int smem_bytes = SMEM_FLOATS * sizeof(float);
    cudaFuncSetAttribute(persist_kernel, cudaFuncAttributeMaxDynamicSharedMemorySize, smem_bytes);

    persist_kernel<<<B * NPAIR, 256, smem_bytes>>>(out, u, x, B, T);
}